// round 4
// baseline (speedup 1.0000x reference)
#include <cuda_runtime.h>

#define NPOOL 100000
#define NUN   200000
#define NEDGE 1200000
#define CH    64
#define EPSV  1e-5f

#define SCAN_BLK   512
#define SCAN_ITEMS 8
#define SCAN_TILE  (SCAN_BLK * SCAN_ITEMS)                 // 4096
#define NSCAN      ((NUN + SCAN_TILE - 1) / SCAN_TILE)     // 49

// ---------------- scratch ----------------
__device__ float  g_P  [NPOOL * CH];    // x @ W1
__device__ float  g_HWp[NPOOL * CH];    // relu(bn1(P/score+b1)) @ Wg
__device__ float  g_ACC[NUN * CH];      // GCN result (pre-BN2)
__device__ int    g_indeg[NUN];
__device__ float  g_dis[NUN];
__device__ int    g_cnt[NPOOL];
__device__ int    g_off[NUN + 1];
__device__ int    g_cur[NUN];
__device__ int2   g_ent[NEDGE];         // {cluster[src], bits(dis[src])} sorted by dst
__device__ int    g_bsum[NSCAN], g_bpre[NSCAN];
__device__ double g_s1[CH], g_q1[CH], g_s2[CH], g_q2[CH];
__device__ float  g_scale1[CH], g_shift1[CH], g_scale2[CH], g_shift2[CH];

// ---------------- init ----------------
__global__ void k_init() {
    int i = blockIdx.x * blockDim.x + threadIdx.x;
    if (i < NUN)   g_indeg[i] = 0;
    if (i < NPOOL) g_cnt[i] = 0;
    if (i < CH) { g_s1[i] = 0.0; g_q1[i] = 0.0; g_s2[i] = 0.0; g_q2[i] = 0.0; }
}

// ---------------- in-degree (dst) + cluster histogram ----------------
__global__ void k_deg_hist(const int* __restrict__ dst, const int* __restrict__ cluster) {
    int i = blockIdx.x * blockDim.x + threadIdx.x;
    if (i < NEDGE) atomicAdd(&g_indeg[dst[i]], 1);
    if (i < NUN)   atomicAdd(&g_cnt[cluster[i]], 1);
}

__global__ void k_dis() {
    int i = blockIdx.x * blockDim.x + threadIdx.x;
    if (i < NUN) g_dis[i] = rsqrtf((float)g_indeg[i] + 1.0f);
}

// ---------------- scan phase A: per-block sums of indeg ----------------
__global__ __launch_bounds__(SCAN_BLK) void k_scanA() {
    __shared__ int sh[SCAN_BLK];
    int t = threadIdx.x;
    int base = blockIdx.x * SCAN_TILE + t * SCAN_ITEMS;
    int s = 0;
#pragma unroll
    for (int i = 0; i < SCAN_ITEMS; i++) {
        int idx = base + i;
        if (idx < NUN) s += g_indeg[idx];
    }
    sh[t] = s;
    __syncthreads();
    for (int off = SCAN_BLK / 2; off > 0; off >>= 1) {
        if (t < off) sh[t] += sh[t + off];
        __syncthreads();
    }
    if (t == 0) g_bsum[blockIdx.x] = sh[0];
}

// ---------------- scan phase B: exclusive scan of block sums ----------------
__global__ void k_scanB() {
    if (threadIdx.x == 0) {
        int run = 0;
        for (int b = 0; b < NSCAN; b++) { g_bpre[b] = run; run += g_bsum[b]; }
        g_off[NUN] = run;   // == NEDGE
    }
}

// ---------------- scan phase C: write exclusive offsets + cursor ----------------
__global__ __launch_bounds__(SCAN_BLK) void k_scanC() {
    __shared__ int wsum[16];
    int t = threadIdx.x;
    int lane = t & 31, wid = t >> 5;
    int base = blockIdx.x * SCAN_TILE + t * SCAN_ITEMS;
    int v[SCAN_ITEMS];
    int s = 0;
#pragma unroll
    for (int i = 0; i < SCAN_ITEMS; i++) {
        int idx = base + i;
        v[i] = (idx < NUN) ? g_indeg[idx] : 0;
        s += v[i];
    }
    int incl = s;
#pragma unroll
    for (int off = 1; off < 32; off <<= 1) {
        int n = __shfl_up_sync(0xFFFFFFFFu, incl, off);
        if (lane >= off) incl += n;
    }
    if (lane == 31) wsum[wid] = incl;
    __syncthreads();
    if (wid == 0) {
        int x = (lane < 16) ? wsum[lane] : 0;
        int xi = x;
#pragma unroll
        for (int off = 1; off < 32; off <<= 1) {
            int n = __shfl_up_sync(0xFFFFFFFFu, xi, off);
            if (lane >= off) xi += n;
        }
        if (lane < 16) wsum[lane] = xi - x;   // exclusive warp prefix
    }
    __syncthreads();
    int run = g_bpre[blockIdx.x] + wsum[wid] + (incl - s);
#pragma unroll
    for (int i = 0; i < SCAN_ITEMS; i++) {
        int idx = base + i;
        if (idx < NUN) { g_off[idx] = run; g_cur[idx] = run; run += v[i]; }
    }
}

// ---------------- fill: bucket edges by dst, store {cluster[src], dis[src]} ----------------
__global__ void k_fill(const int* __restrict__ src, const int* __restrict__ dst,
                       const int* __restrict__ cluster) {
    int e = blockIdx.x * blockDim.x + threadIdx.x;
    if (e < NEDGE) {
        int s = src[e], d = dst[e];
        int pos = atomicAdd(&g_cur[d], 1);
        g_ent[pos] = make_int2(cluster[s], __float_as_int(g_dis[s]));
    }
}

// ---------------- GEMM1: P = x @ W1 ----------------
__global__ __launch_bounds__(128) void k_gemm1(const float* __restrict__ x,
                                               const float* __restrict__ W) {
    __shared__ float Ws[64 * 64];
    __shared__ float Xs[64 * 68];
    int t = threadIdx.x;
    for (int i = t; i < 1024; i += 128)
        ((float4*)Ws)[i] = ((const float4*)W)[i];
    int row0 = blockIdx.x * 64;
    for (int i = t; i < 1024; i += 128) {
        int r = i >> 4, c4 = i & 15;
        int row = row0 + r;
        float4 v = make_float4(0.f, 0.f, 0.f, 0.f);
        if (row < NPOOL) v = ((const float4*)(x + (size_t)row * CH))[c4];
        *((float4*)(Xs + r * 68 + c4 * 4)) = v;
    }
    __syncthreads();
    int cg = t & 7, rg = t >> 3;
    float acc[4][8];
#pragma unroll
    for (int r = 0; r < 4; r++)
#pragma unroll
        for (int c = 0; c < 8; c++) acc[r][c] = 0.f;
    for (int k = 0; k < 64; k++) {
        float4 w0 = *((float4*)(Ws + k * 64 + cg * 8));
        float4 w1 = *((float4*)(Ws + k * 64 + cg * 8 + 4));
#pragma unroll
        for (int r = 0; r < 4; r++) {
            float xv = Xs[(rg + 16 * r) * 68 + k];
            acc[r][0] = fmaf(xv, w0.x, acc[r][0]);
            acc[r][1] = fmaf(xv, w0.y, acc[r][1]);
            acc[r][2] = fmaf(xv, w0.z, acc[r][2]);
            acc[r][3] = fmaf(xv, w0.w, acc[r][3]);
            acc[r][4] = fmaf(xv, w1.x, acc[r][4]);
            acc[r][5] = fmaf(xv, w1.y, acc[r][5]);
            acc[r][6] = fmaf(xv, w1.z, acc[r][6]);
            acc[r][7] = fmaf(xv, w1.w, acc[r][7]);
        }
    }
#pragma unroll
    for (int r = 0; r < 4; r++) {
        int row = row0 + rg + 16 * r;
        if (row < NPOOL) {
            size_t base = (size_t)row * CH + cg * 8;
            *((float4*)(g_P + base))     = make_float4(acc[r][0], acc[r][1], acc[r][2], acc[r][3]);
            *((float4*)(g_P + base + 4)) = make_float4(acc[r][4], acc[r][5], acc[r][6], acc[r][7]);
        }
    }
}

// ---------------- BN1 stats from P weighted by cnt (grid-stride, low-contention) ----------------
__global__ void k_stats1(const float* __restrict__ score, const float* __restrict__ b1) {
    int tx = threadIdx.x, ty = threadIdx.y;
    float bias = b1[tx];
    float ls = 0.f, lq = 0.f;
    for (int row = blockIdx.x * 4 + ty; row < NPOOL; row += gridDim.x * 4) {
        int w = g_cnt[row];
        if (w > 0) {
            float inv = 1.0f / score[row];
            float v = fmaf(g_P[(size_t)row * CH + tx], inv, bias);
            float fw = (float)w;
            ls = fmaf(fw, v, ls);
            lq = fmaf(fw * v, v, lq);
        }
    }
    __shared__ float ss[4][64], sq[4][64];
    ss[ty][tx] = ls; sq[ty][tx] = lq;
    __syncthreads();
    if (ty == 0) {
        float s = ss[0][tx] + ss[1][tx] + ss[2][tx] + ss[3][tx];
        float q = sq[0][tx] + sq[1][tx] + sq[2][tx] + sq[3][tx];
        atomicAdd(&g_s1[tx], (double)s);
        atomicAdd(&g_q1[tx], (double)q);
    }
}

// ---------------- finalize BN params ----------------
__global__ void k_meanvar(const float* __restrict__ g, const float* __restrict__ b, int which) {
    int t = threadIdx.x;
    if (t < CH) {
        double s = which ? g_s2[t] : g_s1[t];
        double q = which ? g_q2[t] : g_q1[t];
        double invN = 1.0 / (double)NUN;
        float mu = (float)(s * invN);
        float var = (float)(q * invN) - mu * mu;
        if (var < 0.f) var = 0.f;
        float rs = rsqrtf(var + EPSV);
        float sc = g[t] * rs;
        float sh = b[t] - mu * sc;
        if (which) { g_scale2[t] = sc; g_shift2[t] = sh; }
        else       { g_scale1[t] = sc; g_shift1[t] = sh; }
    }
}

// ---------------- GEMM2 on pooled rows: HWp = relu(bn1(P/score + b1)) @ Wg ----------------
__global__ __launch_bounds__(128) void k_gemm2(const float* __restrict__ Wg,
                                               const float* __restrict__ score,
                                               const float* __restrict__ b1) {
    __shared__ float Ws[64 * 64];
    __shared__ float Xs[64 * 68];
    int t = threadIdx.x;
    for (int i = t; i < 1024; i += 128)
        ((float4*)Ws)[i] = ((const float4*)Wg)[i];
    int row0 = blockIdx.x * 64;
    for (int i = t; i < 1024; i += 128) {
        int r = i >> 4, c4 = i & 15;
        int row = row0 + r;
        float4 v = make_float4(0.f, 0.f, 0.f, 0.f);
        if (row < NPOOL) {
            float inv = 1.0f / score[row];
            float4 p   = ((const float4*)(g_P + (size_t)row * CH))[c4];
            float4 a   = ((const float4*)g_scale1)[c4];
            float4 sh  = ((const float4*)g_shift1)[c4];
            float4 b1v = ((const float4*)b1)[c4];
            v.x = fmaxf(fmaf(p.x * inv, a.x, fmaf(b1v.x, a.x, sh.x)), 0.f);
            v.y = fmaxf(fmaf(p.y * inv, a.y, fmaf(b1v.y, a.y, sh.y)), 0.f);
            v.z = fmaxf(fmaf(p.z * inv, a.z, fmaf(b1v.z, a.z, sh.z)), 0.f);
            v.w = fmaxf(fmaf(p.w * inv, a.w, fmaf(b1v.w, a.w, sh.w)), 0.f);
        }
        *((float4*)(Xs + r * 68 + c4 * 4)) = v;
    }
    __syncthreads();
    int cg = t & 7, rg = t >> 3;
    float acc[4][8];
#pragma unroll
    for (int r = 0; r < 4; r++)
#pragma unroll
        for (int c = 0; c < 8; c++) acc[r][c] = 0.f;
    for (int k = 0; k < 64; k++) {
        float4 w0 = *((float4*)(Ws + k * 64 + cg * 8));
        float4 w1 = *((float4*)(Ws + k * 64 + cg * 8 + 4));
#pragma unroll
        for (int r = 0; r < 4; r++) {
            float xv = Xs[(rg + 16 * r) * 68 + k];
            acc[r][0] = fmaf(xv, w0.x, acc[r][0]);
            acc[r][1] = fmaf(xv, w0.y, acc[r][1]);
            acc[r][2] = fmaf(xv, w0.z, acc[r][2]);
            acc[r][3] = fmaf(xv, w0.w, acc[r][3]);
            acc[r][4] = fmaf(xv, w1.x, acc[r][4]);
            acc[r][5] = fmaf(xv, w1.y, acc[r][5]);
            acc[r][6] = fmaf(xv, w1.z, acc[r][6]);
            acc[r][7] = fmaf(xv, w1.w, acc[r][7]);
        }
    }
#pragma unroll
    for (int r = 0; r < 4; r++) {
        int row = row0 + rg + 16 * r;
        if (row < NPOOL) {
            size_t base = (size_t)row * CH + cg * 8;
            *((float4*)(g_HWp + base))     = make_float4(acc[r][0], acc[r][1], acc[r][2], acc[r][3]);
            *((float4*)(g_HWp + base + 4)) = make_float4(acc[r][4], acc[r][5], acc[r][6], acc[r][7]);
        }
    }
}

// ---------------- gather: ACC[d] = bg + HWp[cluster[d]]*dis[d]^2 + sum_in-edges ----------------
// 16 threads per dst row (q = float4 chunk), register accumulation, one store.
__global__ __launch_bounds__(256) void k_gather(const int* __restrict__ cluster,
                                                const float* __restrict__ bg) {
    int t = threadIdx.x;
    int rowIdx = t >> 4;
    int q = t & 15;
    int d = blockIdx.x * 16 + rowIdx;
    if (d >= NUN) return;
    int   c0 = cluster[d];
    float dd = g_dis[d];
    float d2 = dd * dd;
    float4 acc = ((const float4*)bg)[q];
    float4 h0  = ((const float4*)(g_HWp + (size_t)c0 * CH))[q];
    acc.x = fmaf(h0.x, d2, acc.x);
    acc.y = fmaf(h0.y, d2, acc.y);
    acc.z = fmaf(h0.z, d2, acc.z);
    acc.w = fmaf(h0.w, d2, acc.w);
    int beg = g_off[d], end = g_off[d + 1];
    for (int j = beg; j < end; j++) {
        int2 ent = g_ent[j];                       // broadcast across 16 threads
        float coef = __int_as_float(ent.y) * dd;
        float4 h = ((const float4*)(g_HWp + (size_t)ent.x * CH))[q];
        acc.x = fmaf(h.x, coef, acc.x);
        acc.y = fmaf(h.y, coef, acc.y);
        acc.z = fmaf(h.z, coef, acc.z);
        acc.w = fmaf(h.w, coef, acc.w);
    }
    ((float4*)(g_ACC + (size_t)d * CH))[q] = acc;
}

// ---------------- BN2 stats over ACC (grid-stride, low-contention) ----------------
__global__ void k_stats2() {
    int tx = threadIdx.x, ty = threadIdx.y;
    float ls = 0.f, lq = 0.f;
    for (int row = blockIdx.x * 4 + ty; row < NUN; row += gridDim.x * 4) {
        float v = g_ACC[(size_t)row * CH + tx];
        ls += v;
        lq += v * v;
    }
    __shared__ float ss[4][64], sq[4][64];
    ss[ty][tx] = ls; sq[ty][tx] = lq;
    __syncthreads();
    if (ty == 0) {
        float s = ss[0][tx] + ss[1][tx] + ss[2][tx] + ss[3][tx];
        float q = sq[0][tx] + sq[1][tx] + sq[2][tx] + sq[3][tx];
        atomicAdd(&g_s2[tx], (double)s);
        atomicAdd(&g_q2[tx], (double)q);
    }
}

// ---------------- final: out = relu(bn2(ACC)) ----------------
__global__ void k_final(float* __restrict__ out) {
    int i4 = blockIdx.x * blockDim.x + threadIdx.x;
    if (i4 < NUN * 16) {
        int c4 = i4 & 15;
        float4 v  = ((const float4*)g_ACC)[i4];
        float4 sc = ((const float4*)g_scale2)[c4];
        float4 sh = ((const float4*)g_shift2)[c4];
        float4 o;
        o.x = fmaxf(fmaf(v.x, sc.x, sh.x), 0.f);
        o.y = fmaxf(fmaf(v.y, sc.y, sh.y), 0.f);
        o.z = fmaxf(fmaf(v.z, sc.z, sh.z), 0.f);
        o.w = fmaxf(fmaf(v.w, sc.w, sh.w), 0.f);
        ((float4*)out)[i4] = o;
    }
}

// ---------------- optional tail: edge_index + batch passthrough ----------------
__global__ void k_tail(const int* __restrict__ ei, const int* __restrict__ batch,
                       float* __restrict__ out, int extra) {
    int i = blockIdx.x * blockDim.x + threadIdx.x;
    if (i < extra) {
        float v;
        if (i < 2 * NEDGE) v = (float)ei[i];
        else {
            int j = i - 2 * NEDGE;
            v = (j < NUN) ? (float)batch[j] : 0.f;
        }
        out[NUN * CH + i] = v;
    }
}

// ---------------- launch ----------------
extern "C" void kernel_launch(void* const* d_in, const int* in_sizes, int n_in,
                              void* d_out, int out_size) {
    const float* x       = (const float*)d_in[0];
    const int*   ei      = (const int*)  d_in[1];
    const int*   batch   = (const int*)  d_in[2];
    const int*   cluster = (const int*)  d_in[3];
    const float* score   = (const float*)d_in[4];
    const float* W1      = (const float*)d_in[5];
    const float* b1      = (const float*)d_in[6];
    const float* g1      = (const float*)d_in[7];
    const float* be1     = (const float*)d_in[8];
    const float* Wg      = (const float*)d_in[9];
    const float* bg      = (const float*)d_in[10];
    const float* g2      = (const float*)d_in[11];
    const float* be2     = (const float*)d_in[12];
    const int* srcA = ei;
    const int* dstA = ei + NEDGE;
    float* out = (float*)d_out;

    k_init<<<(NUN + 255) / 256, 256>>>();
    k_deg_hist<<<(NEDGE + 255) / 256, 256>>>(dstA, cluster);
    k_dis<<<(NUN + 255) / 256, 256>>>();
    k_scanA<<<NSCAN, SCAN_BLK>>>();
    k_scanB<<<1, 32>>>();
    k_scanC<<<NSCAN, SCAN_BLK>>>();
    k_fill<<<(NEDGE + 255) / 256, 256>>>(srcA, dstA, cluster);
    k_gemm1<<<(NPOOL + 63) / 64, 128>>>(x, W1);
    k_stats1<<<264, dim3(64, 4)>>>(score, b1);
    k_meanvar<<<1, 64>>>(g1, be1, 0);
    k_gemm2<<<(NPOOL + 63) / 64, 128>>>(Wg, score, b1);
    k_gather<<<(NUN + 15) / 16, 256>>>(cluster, bg);
    k_stats2<<<264, dim3(64, 4)>>>();
    k_meanvar<<<1, 64>>>(g2, be2, 1);
    k_final<<<(NUN * 16 + 255) / 256, 256>>>(out);

    int extra = out_size - NUN * CH;
    if (extra > 0)
        k_tail<<<(extra + 255) / 256, 256>>>(ei, batch, out, extra);
}